// round 1
// baseline (speedup 1.0000x reference)
#include <cuda_runtime.h>
#include <math_constants.h>

#define NN 100000
#define EE 1000000
#define NHE 20000
#define D 128
#define NHEAD 4
#define DKK 32

// ---------------- scratch (device globals: no allocation allowed) ------------
__device__ __align__(16) float g_hnode[NN * D];      // x@Wk+bk
__device__ __align__(16) float g_q[NN * D];          // x@Wq+bq
__device__ __align__(16) float g_hef[NHE * D];       // hyperedge features
__device__ __align__(16) float g_alpha[EE * NHEAD];  // per-edge scores
__device__ __align__(16) float g_m[NN * NHEAD];      // per-node per-head max
__device__ __align__(16) float g_s[NN * NHEAD];      // per-node per-head sum of exp
__device__ __align__(16) float g_nacc[NN * D];       // unnormalized node output

// ---------------- helpers ----------------------------------------------------
__device__ __forceinline__ void redAdd4(float4* p, float a, float b, float c, float d) {
    asm volatile("red.global.add.v4.f32 [%0], {%1,%2,%3,%4};"
                 :: "l"(p), "f"(a), "f"(b), "f"(c), "f"(d) : "memory");
}

__device__ __forceinline__ void atomicMaxF(float* addr, float v) {
    if (v >= 0.f) atomicMax((int*)addr, __float_as_int(v));
    else          atomicMin((unsigned int*)addr, __float_as_uint(v));
}

// ---------------- init -------------------------------------------------------
__global__ void k_init() {
    int i = blockIdx.x * 256 + threadIdx.x;
    float4 z = make_float4(0.f, 0.f, 0.f, 0.f);
    float4 ninf = make_float4(-CUDART_INF_F, -CUDART_INF_F, -CUDART_INF_F, -CUDART_INF_F);
    if (i < NN * D / 4) ((float4*)g_nacc)[i] = z;
    if (i < NHE * D / 4) ((float4*)g_hef)[i] = z;
    if (i < NN) { ((float4*)g_s)[i] = z; ((float4*)g_m)[i] = ninf; }
}

// ---------------- GEMM 1: h_node = x@Wk+bk, q = x@Wq+bq ----------------------
__global__ __launch_bounds__(256, 2) void k_gemm_kq(
    const float* __restrict__ x,
    const float* __restrict__ Wk, const float* __restrict__ bk,
    const float* __restrict__ Wq, const float* __restrict__ bq) {
    __shared__ __align__(16) float sA[64][33];
    __shared__ __align__(16) float sK[32][128];
    __shared__ __align__(16) float sQ[32][128];
    const int tid = threadIdx.x;
    const int tx = tid & 15, ty = tid >> 4;
    const int row0 = blockIdx.x * 64;

    float aK[4][8], aQ[4][8];
#pragma unroll
    for (int i = 0; i < 4; i++)
#pragma unroll
        for (int j = 0; j < 8; j++) { aK[i][j] = 0.f; aQ[i][j] = 0.f; }

    for (int kb = 0; kb < 4; kb++) {
#pragma unroll
        for (int t = 0; t < 2; t++) {
            int slot = tid * 2 + t;
            int r = slot >> 3;
            int c = (slot & 7) * 4;
            float4 v = make_float4(0.f, 0.f, 0.f, 0.f);
            int row = row0 + r;
            if (row < NN) v = *(const float4*)(x + row * 128 + kb * 32 + c);
            sA[r][c] = v.x; sA[r][c + 1] = v.y; sA[r][c + 2] = v.z; sA[r][c + 3] = v.w;
        }
#pragma unroll
        for (int t = 0; t < 4; t++) {
            int slot = tid * 4 + t;
            int r = slot >> 5;
            int c = (slot & 31) * 4;
            *(float4*)&sK[r][c] = *(const float4*)(Wk + (kb * 32 + r) * 128 + c);
            *(float4*)&sQ[r][c] = *(const float4*)(Wq + (kb * 32 + r) * 128 + c);
        }
        __syncthreads();
#pragma unroll 8
        for (int k = 0; k < 32; k++) {
            float a[4];
#pragma unroll
            for (int i = 0; i < 4; i++) a[i] = sA[ty * 4 + i][k];
            float4 k0 = *(float4*)&sK[k][tx * 8];
            float4 k1 = *(float4*)&sK[k][tx * 8 + 4];
            float4 q0 = *(float4*)&sQ[k][tx * 8];
            float4 q1 = *(float4*)&sQ[k][tx * 8 + 4];
#pragma unroll
            for (int i = 0; i < 4; i++) {
                aK[i][0] += a[i] * k0.x; aK[i][1] += a[i] * k0.y;
                aK[i][2] += a[i] * k0.z; aK[i][3] += a[i] * k0.w;
                aK[i][4] += a[i] * k1.x; aK[i][5] += a[i] * k1.y;
                aK[i][6] += a[i] * k1.z; aK[i][7] += a[i] * k1.w;
                aQ[i][0] += a[i] * q0.x; aQ[i][1] += a[i] * q0.y;
                aQ[i][2] += a[i] * q0.z; aQ[i][3] += a[i] * q0.w;
                aQ[i][4] += a[i] * q1.x; aQ[i][5] += a[i] * q1.y;
                aQ[i][6] += a[i] * q1.z; aQ[i][7] += a[i] * q1.w;
            }
        }
        __syncthreads();
    }
    float4 bk0 = *(const float4*)(bk + tx * 8), bk1 = *(const float4*)(bk + tx * 8 + 4);
    float4 bq0 = *(const float4*)(bq + tx * 8), bq1 = *(const float4*)(bq + tx * 8 + 4);
#pragma unroll
    for (int i = 0; i < 4; i++) {
        int row = row0 + ty * 4 + i;
        if (row >= NN) continue;
        float4 o;
        o.x = aK[i][0] + bk0.x; o.y = aK[i][1] + bk0.y; o.z = aK[i][2] + bk0.z; o.w = aK[i][3] + bk0.w;
        *(float4*)(g_hnode + row * 128 + tx * 8) = o;
        o.x = aK[i][4] + bk1.x; o.y = aK[i][5] + bk1.y; o.z = aK[i][6] + bk1.z; o.w = aK[i][7] + bk1.w;
        *(float4*)(g_hnode + row * 128 + tx * 8 + 4) = o;
        o.x = aQ[i][0] + bq0.x; o.y = aQ[i][1] + bq0.y; o.z = aQ[i][2] + bq0.z; o.w = aQ[i][3] + bq0.w;
        *(float4*)(g_q + row * 128 + tx * 8) = o;
        o.x = aQ[i][4] + bq1.x; o.y = aQ[i][5] + bq1.y; o.z = aQ[i][6] + bq1.z; o.w = aQ[i][7] + bq1.w;
        *(float4*)(g_q + row * 128 + tx * 8 + 4) = o;
    }
}

// ---------------- edge pass 1: he_feat[he] += h_node[node] -------------------
__global__ void k_heagg(const int* __restrict__ ni, const int* __restrict__ hi) {
    int g = blockIdx.x * 256 + threadIdx.x;
    int e = g >> 5, lane = g & 31;
    int node = ni[e], he = hi[e];
    float4 v = ((const float4*)g_hnode)[node * 32 + lane];
    redAdd4(((float4*)g_hef) + he * 32 + lane, v.x, v.y, v.z, v.w);
}

// ---------------- edge pass 2: alpha + per-node max --------------------------
__global__ void k_alpha(const int* __restrict__ ni, const int* __restrict__ hi) {
    int g = blockIdx.x * 256 + threadIdx.x;
    int e = g >> 5, lane = g & 31;
    int node = ni[e], he = hi[e];
    float4 qv = ((const float4*)g_q)[node * 32 + lane];
    float4 hv = ((const float4*)g_hef)[he * 32 + lane];
    float p = qv.x * hv.x + qv.y * hv.y + qv.z * hv.z + qv.w * hv.w;
    p += __shfl_xor_sync(0xffffffffu, p, 4);
    p += __shfl_xor_sync(0xffffffffu, p, 2);
    p += __shfl_xor_sync(0xffffffffu, p, 1);
    int head = lane >> 3;
    if ((lane & 7) == 0) {
        float a = p * 0.17677669529663687f;  // 1/sqrt(32)
        g_alpha[e * 4 + head] = a;
        atomicMaxF(&g_m[node * 4 + head], a);
    }
}

// ---------------- edge pass 3: node_acc += exp(a-m)*he_feat; s += exp -------
__global__ void k_accum(const int* __restrict__ ni, const int* __restrict__ hi) {
    int g = blockIdx.x * 256 + threadIdx.x;
    int e = g >> 5, lane = g & 31;
    int node = ni[e], he = hi[e];
    int head = lane >> 3;
    float a = g_alpha[e * 4 + head];
    float mm = g_m[node * 4 + head];
    float ev = __expf(a - mm);
    float4 hv = ((const float4*)g_hef)[he * 32 + lane];
    redAdd4(((float4*)g_nacc) + node * 32 + lane, ev * hv.x, ev * hv.y, ev * hv.z, ev * hv.w);
    if ((lane & 7) == 0) atomicAdd(&g_s[node * 4 + head], ev);
}

// ---------------- final: out = (node_acc/s + x) @ Wa + ba --------------------
__global__ __launch_bounds__(256, 2) void k_gemm_out(
    const float* __restrict__ x,
    const float* __restrict__ Wa, const float* __restrict__ ba,
    float* __restrict__ out) {
    __shared__ __align__(16) float sA[64][33];
    __shared__ __align__(16) float sW[32][128];
    const int tid = threadIdx.x;
    const int tx = tid & 15, ty = tid >> 4;
    const int row0 = blockIdx.x * 64;

    float acc[4][8];
#pragma unroll
    for (int i = 0; i < 4; i++)
#pragma unroll
        for (int j = 0; j < 8; j++) acc[i][j] = 0.f;

    for (int kb = 0; kb < 4; kb++) {  // k-chunk of 32 == one head
#pragma unroll
        for (int t = 0; t < 2; t++) {
            int slot = tid * 2 + t;
            int r = slot >> 3;
            int c = (slot & 7) * 4;
            float4 v = make_float4(0.f, 0.f, 0.f, 0.f);
            int row = row0 + r;
            if (row < NN) {
                float4 xv = *(const float4*)(x + row * 128 + kb * 32 + c);
                float4 nv = *(const float4*)(g_nacc + row * 128 + kb * 32 + c);
                float inv = 1.f / (g_s[row * 4 + kb] + 1e-16f);
                v.x = nv.x * inv + xv.x; v.y = nv.y * inv + xv.y;
                v.z = nv.z * inv + xv.z; v.w = nv.w * inv + xv.w;
            }
            sA[r][c] = v.x; sA[r][c + 1] = v.y; sA[r][c + 2] = v.z; sA[r][c + 3] = v.w;
        }
#pragma unroll
        for (int t = 0; t < 4; t++) {
            int slot = tid * 4 + t;
            int r = slot >> 5;
            int c = (slot & 31) * 4;
            *(float4*)&sW[r][c] = *(const float4*)(Wa + (kb * 32 + r) * 128 + c);
        }
        __syncthreads();
#pragma unroll 8
        for (int k = 0; k < 32; k++) {
            float a[4];
#pragma unroll
            for (int i = 0; i < 4; i++) a[i] = sA[ty * 4 + i][k];
            float4 w0 = *(float4*)&sW[k][tx * 8];
            float4 w1 = *(float4*)&sW[k][tx * 8 + 4];
#pragma unroll
            for (int i = 0; i < 4; i++) {
                acc[i][0] += a[i] * w0.x; acc[i][1] += a[i] * w0.y;
                acc[i][2] += a[i] * w0.z; acc[i][3] += a[i] * w0.w;
                acc[i][4] += a[i] * w1.x; acc[i][5] += a[i] * w1.y;
                acc[i][6] += a[i] * w1.z; acc[i][7] += a[i] * w1.w;
            }
        }
        __syncthreads();
    }
    float4 b0 = *(const float4*)(ba + tx * 8), b1 = *(const float4*)(ba + tx * 8 + 4);
#pragma unroll
    for (int i = 0; i < 4; i++) {
        int row = row0 + ty * 4 + i;
        if (row >= NN) continue;
        float4 o;
        o.x = acc[i][0] + b0.x; o.y = acc[i][1] + b0.y; o.z = acc[i][2] + b0.z; o.w = acc[i][3] + b0.w;
        *(float4*)(out + row * 128 + tx * 8) = o;
        o.x = acc[i][4] + b1.x; o.y = acc[i][5] + b1.y; o.z = acc[i][6] + b1.z; o.w = acc[i][7] + b1.w;
        *(float4*)(out + row * 128 + tx * 8 + 4) = o;
    }
}

// ---------------- launch -----------------------------------------------------
extern "C" void kernel_launch(void* const* d_in, const int* in_sizes, int n_in,
                              void* d_out, int out_size) {
    const float* x  = (const float*)d_in[0];
    const int*   ni = (const int*)d_in[1];
    const int*   hi = (const int*)d_in[2];
    const float* Wk = (const float*)d_in[3];
    const float* bk = (const float*)d_in[4];
    const float* Wq = (const float*)d_in[5];
    const float* bq = (const float*)d_in[6];
    const float* Wa = (const float*)d_in[7];
    const float* ba = (const float*)d_in[8];
    float* out = (float*)d_out;

    k_init<<<(NN * D / 4 + 255) / 256, 256>>>();
    k_gemm_kq<<<(NN + 63) / 64, 256>>>(x, Wk, bk, Wq, bq);
    k_heagg<<<EE * 32 / 256, 256>>>(ni, hi);
    k_alpha<<<EE * 32 / 256, 256>>>(ni, hi);
    k_accum<<<EE * 32 / 256, 256>>>(ni, hi);
    k_gemm_out<<<(NN + 63) / 64, 256>>>(x, Wa, ba, out);
}

// round 2
// speedup vs baseline: 1.0392x; 1.0392x over previous
#include <cuda_runtime.h>
#include <math_constants.h>

#define NN 100000
#define EE 1000000
#define NHE 20000
#define D 128
#define NHEAD 4
#define FULL 0xffffffffu

// ---------------- scratch (device globals: no allocation allowed) ------------
__device__ __align__(16) float g_hnode[NN * D];   // x@Wk+bk
__device__ __align__(16) float g_q[NN * D];       // x@Wq+bq
__device__ __align__(16) float g_hef[NHE * D];    // hyperedge features
__device__ __align__(16) float g_resid[NN * D];   // normalized attn out + x

__device__ int g_cnt_he[NHE], g_cnt_n[NN];
__device__ int g_off_he[NHE + 1], g_off_n[NN + 1];
__device__ int g_cur_he[NHE], g_cur_n[NN];
__device__ int g_he_nodes[EE];   // node ids grouped by hyperedge
__device__ int g_n_hes[EE];      // hyperedge ids grouped by node

// ---------------- CSR build --------------------------------------------------
__global__ void k_zero() {
    int i = blockIdx.x * 256 + threadIdx.x;
    if (i < NHE) g_cnt_he[i] = 0;
    if (i < NN) g_cnt_n[i] = 0;
}

__global__ void k_hist(const int* __restrict__ ni, const int* __restrict__ hi) {
    int e = blockIdx.x * 256 + threadIdx.x;
    if (e < EE) {
        atomicAdd(&g_cnt_he[hi[e]], 1);
        atomicAdd(&g_cnt_n[ni[e]], 1);
    }
}

// single-block exclusive scan over M counters -> off[M+1], cur[i]=off[i]
__global__ void k_scan(const int* __restrict__ cnt, int* __restrict__ off,
                       int* __restrict__ cur, int M) {
    __shared__ int part[1024];
    int t = threadIdx.x;
    int chunk = (M + 1023) >> 10;
    int lo = min(t * chunk, M), hi = min(lo + chunk, M);
    int sum = 0;
    for (int i = lo; i < hi; i++) sum += cnt[i];
    part[t] = sum;
    __syncthreads();
    for (int d = 1; d < 1024; d <<= 1) {
        int v = (t >= d) ? part[t - d] : 0;
        __syncthreads();
        part[t] += v;
        __syncthreads();
    }
    int run = part[t] - sum;  // exclusive prefix
    for (int i = lo; i < hi; i++) { off[i] = run; cur[i] = run; run += cnt[i]; }
    if (hi == M) off[M] = run;
}

__global__ void k_scatter(const int* __restrict__ ni, const int* __restrict__ hi) {
    int e = blockIdx.x * 256 + threadIdx.x;
    if (e < EE) {
        int n = ni[e], he = hi[e];
        int p = atomicAdd(&g_cur_he[he], 1);
        g_he_nodes[p] = n;
        int p2 = atomicAdd(&g_cur_n[n], 1);
        g_n_hes[p2] = he;
    }
}

// ---------------- GEMM 1: h_node = x@Wk+bk, q = x@Wq+bq ----------------------
__global__ __launch_bounds__(256, 2) void k_gemm_kq(
    const float* __restrict__ x,
    const float* __restrict__ Wk, const float* __restrict__ bk,
    const float* __restrict__ Wq, const float* __restrict__ bq) {
    __shared__ __align__(16) float sA[64][33];
    __shared__ __align__(16) float sK[32][128];
    __shared__ __align__(16) float sQ[32][128];
    const int tid = threadIdx.x;
    const int tx = tid & 15, ty = tid >> 4;
    const int row0 = blockIdx.x * 64;

    float aK[4][8], aQ[4][8];
#pragma unroll
    for (int i = 0; i < 4; i++)
#pragma unroll
        for (int j = 0; j < 8; j++) { aK[i][j] = 0.f; aQ[i][j] = 0.f; }

    for (int kb = 0; kb < 4; kb++) {
#pragma unroll
        for (int t = 0; t < 2; t++) {
            int slot = tid * 2 + t;
            int r = slot >> 3;
            int c = (slot & 7) * 4;
            float4 v = make_float4(0.f, 0.f, 0.f, 0.f);
            int row = row0 + r;
            if (row < NN) v = *(const float4*)(x + row * 128 + kb * 32 + c);
            sA[r][c] = v.x; sA[r][c + 1] = v.y; sA[r][c + 2] = v.z; sA[r][c + 3] = v.w;
        }
#pragma unroll
        for (int t = 0; t < 4; t++) {
            int slot = tid * 4 + t;
            int r = slot >> 5;
            int c = (slot & 31) * 4;
            *(float4*)&sK[r][c] = *(const float4*)(Wk + (kb * 32 + r) * 128 + c);
            *(float4*)&sQ[r][c] = *(const float4*)(Wq + (kb * 32 + r) * 128 + c);
        }
        __syncthreads();
#pragma unroll 8
        for (int k = 0; k < 32; k++) {
            float a[4];
#pragma unroll
            for (int i = 0; i < 4; i++) a[i] = sA[ty * 4 + i][k];
            float4 k0 = *(float4*)&sK[k][tx * 8];
            float4 k1 = *(float4*)&sK[k][tx * 8 + 4];
            float4 q0 = *(float4*)&sQ[k][tx * 8];
            float4 q1 = *(float4*)&sQ[k][tx * 8 + 4];
#pragma unroll
            for (int i = 0; i < 4; i++) {
                aK[i][0] += a[i] * k0.x; aK[i][1] += a[i] * k0.y;
                aK[i][2] += a[i] * k0.z; aK[i][3] += a[i] * k0.w;
                aK[i][4] += a[i] * k1.x; aK[i][5] += a[i] * k1.y;
                aK[i][6] += a[i] * k1.z; aK[i][7] += a[i] * k1.w;
                aQ[i][0] += a[i] * q0.x; aQ[i][1] += a[i] * q0.y;
                aQ[i][2] += a[i] * q0.z; aQ[i][3] += a[i] * q0.w;
                aQ[i][4] += a[i] * q1.x; aQ[i][5] += a[i] * q1.y;
                aQ[i][6] += a[i] * q1.z; aQ[i][7] += a[i] * q1.w;
            }
        }
        __syncthreads();
    }
    float4 bk0 = *(const float4*)(bk + tx * 8), bk1 = *(const float4*)(bk + tx * 8 + 4);
    float4 bq0 = *(const float4*)(bq + tx * 8), bq1 = *(const float4*)(bq + tx * 8 + 4);
#pragma unroll
    for (int i = 0; i < 4; i++) {
        int row = row0 + ty * 4 + i;
        if (row >= NN) continue;
        float4 o;
        o.x = aK[i][0] + bk0.x; o.y = aK[i][1] + bk0.y; o.z = aK[i][2] + bk0.z; o.w = aK[i][3] + bk0.w;
        *(float4*)(g_hnode + row * 128 + tx * 8) = o;
        o.x = aK[i][4] + bk1.x; o.y = aK[i][5] + bk1.y; o.z = aK[i][6] + bk1.z; o.w = aK[i][7] + bk1.w;
        *(float4*)(g_hnode + row * 128 + tx * 8 + 4) = o;
        o.x = aQ[i][0] + bq0.x; o.y = aQ[i][1] + bq0.y; o.z = aQ[i][2] + bq0.z; o.w = aQ[i][3] + bq0.w;
        *(float4*)(g_q + row * 128 + tx * 8) = o;
        o.x = aQ[i][4] + bq1.x; o.y = aQ[i][5] + bq1.y; o.z = aQ[i][6] + bq1.z; o.w = aQ[i][7] + bq1.w;
        *(float4*)(g_q + row * 128 + tx * 8 + 4) = o;
    }
}

// ---------------- pass A: per-hyperedge aggregation (no atomics) -------------
__global__ void k_heagg(int dummy) {
    int g = blockIdx.x * 256 + threadIdx.x;
    int he = g >> 5, lane = g & 31;
    if (he >= NHE) return;
    int s = g_off_he[he], e = g_off_he[he + 1];
    float4 acc = make_float4(0.f, 0.f, 0.f, 0.f);
    int base = s;
    // full batches of 32 edges: unrolled for MLP
    for (; base + 32 <= e; base += 32) {
        int myidx = __ldg(&g_he_nodes[base + lane]);
#pragma unroll
        for (int j = 0; j < 32; j += 4) {
            int n0 = __shfl_sync(FULL, myidx, j);
            int n1 = __shfl_sync(FULL, myidx, j + 1);
            int n2 = __shfl_sync(FULL, myidx, j + 2);
            int n3 = __shfl_sync(FULL, myidx, j + 3);
            float4 v0 = ((const float4*)g_hnode)[n0 * 32 + lane];
            float4 v1 = ((const float4*)g_hnode)[n1 * 32 + lane];
            float4 v2 = ((const float4*)g_hnode)[n2 * 32 + lane];
            float4 v3 = ((const float4*)g_hnode)[n3 * 32 + lane];
            acc.x += (v0.x + v1.x) + (v2.x + v3.x);
            acc.y += (v0.y + v1.y) + (v2.y + v3.y);
            acc.z += (v0.z + v1.z) + (v2.z + v3.z);
            acc.w += (v0.w + v1.w) + (v2.w + v3.w);
        }
    }
    if (base < e) {
        int cnt = e - base;
        int myidx = (lane < cnt) ? __ldg(&g_he_nodes[base + lane]) : 0;
        for (int j = 0; j < cnt; j++) {
            int node = __shfl_sync(FULL, myidx, j);
            float4 v = ((const float4*)g_hnode)[node * 32 + lane];
            acc.x += v.x; acc.y += v.y; acc.z += v.z; acc.w += v.w;
        }
    }
    ((float4*)g_hef)[he * 32 + lane] = acc;
}

// ---------------- fused pass B+C: per-node online-softmax attention ----------
__global__ void k_attn(const float* __restrict__ x) {
    int g = blockIdx.x * 256 + threadIdx.x;
    int n = g >> 5, lane = g & 31;
    if (n >= NN) return;
    float4 q4 = ((const float4*)g_q)[n * 32 + lane];
    int s = g_off_n[n], e = g_off_n[n + 1];
    float m = -CUDART_INF_F, ssum = 0.f;
    float4 acc = make_float4(0.f, 0.f, 0.f, 0.f);
    for (int base = s; base < e; base += 32) {
        int cnt = min(32, e - base);
        int myhe = (lane < cnt) ? __ldg(&g_n_hes[base + lane]) : 0;
#pragma unroll 2
        for (int j = 0; j < cnt; j++) {
            int he = __shfl_sync(FULL, myhe, j);
            float4 hv = ((const float4*)g_hef)[he * 32 + lane];
            float p = q4.x * hv.x + q4.y * hv.y + q4.z * hv.z + q4.w * hv.w;
            p += __shfl_xor_sync(FULL, p, 1);
            p += __shfl_xor_sync(FULL, p, 2);
            p += __shfl_xor_sync(FULL, p, 4);   // stays within 8-lane head group
            float alpha = p * 0.17677669529663687f;  // 1/sqrt(32)
            float mn = fmaxf(m, alpha);
            float c = __expf(m - mn);    // 0 on first iter (m=-inf)
            float ev = __expf(alpha - mn);
            ssum = ssum * c + ev;
            acc.x = acc.x * c + ev * hv.x;
            acc.y = acc.y * c + ev * hv.y;
            acc.z = acc.z * c + ev * hv.z;
            acc.w = acc.w * c + ev * hv.w;
            m = mn;
        }
    }
    float inv = 1.f / (ssum + 1e-16f);
    float4 xv = ((const float4*)x)[n * 32 + lane];
    float4 o;
    o.x = acc.x * inv + xv.x; o.y = acc.y * inv + xv.y;
    o.z = acc.z * inv + xv.z; o.w = acc.w * inv + xv.w;
    ((float4*)g_resid)[n * 32 + lane] = o;
}

// ---------------- final: out = g_resid @ Wa + ba -----------------------------
__global__ __launch_bounds__(256, 2) void k_gemm_out(
    const float* __restrict__ Wa, const float* __restrict__ ba,
    float* __restrict__ out) {
    __shared__ __align__(16) float sA[64][33];
    __shared__ __align__(16) float sW[32][128];
    const int tid = threadIdx.x;
    const int tx = tid & 15, ty = tid >> 4;
    const int row0 = blockIdx.x * 64;

    float acc[4][8];
#pragma unroll
    for (int i = 0; i < 4; i++)
#pragma unroll
        for (int j = 0; j < 8; j++) acc[i][j] = 0.f;

    for (int kb = 0; kb < 4; kb++) {
#pragma unroll
        for (int t = 0; t < 2; t++) {
            int slot = tid * 2 + t;
            int r = slot >> 3;
            int c = (slot & 7) * 4;
            float4 v = make_float4(0.f, 0.f, 0.f, 0.f);
            int row = row0 + r;
            if (row < NN) v = *(const float4*)(g_resid + row * 128 + kb * 32 + c);
            sA[r][c] = v.x; sA[r][c + 1] = v.y; sA[r][c + 2] = v.z; sA[r][c + 3] = v.w;
        }
#pragma unroll
        for (int t = 0; t < 4; t++) {
            int slot = tid * 4 + t;
            int r = slot >> 5;
            int c = (slot & 31) * 4;
            *(float4*)&sW[r][c] = *(const float4*)(Wa + (kb * 32 + r) * 128 + c);
        }
        __syncthreads();
#pragma unroll 8
        for (int k = 0; k < 32; k++) {
            float a[4];
#pragma unroll
            for (int i = 0; i < 4; i++) a[i] = sA[ty * 4 + i][k];
            float4 w0 = *(float4*)&sW[k][tx * 8];
            float4 w1 = *(float4*)&sW[k][tx * 8 + 4];
#pragma unroll
            for (int i = 0; i < 4; i++) {
                acc[i][0] += a[i] * w0.x; acc[i][1] += a[i] * w0.y;
                acc[i][2] += a[i] * w0.z; acc[i][3] += a[i] * w0.w;
                acc[i][4] += a[i] * w1.x; acc[i][5] += a[i] * w1.y;
                acc[i][6] += a[i] * w1.z; acc[i][7] += a[i] * w1.w;
            }
        }
        __syncthreads();
    }
    float4 b0 = *(const float4*)(ba + tx * 8), b1 = *(const float4*)(ba + tx * 8 + 4);
#pragma unroll
    for (int i = 0; i < 4; i++) {
        int row = row0 + ty * 4 + i;
        if (row >= NN) continue;
        float4 o;
        o.x = acc[i][0] + b0.x; o.y = acc[i][1] + b0.y; o.z = acc[i][2] + b0.z; o.w = acc[i][3] + b0.w;
        *(float4*)(out + row * 128 + tx * 8) = o;
        o.x = acc[i][4] + b1.x; o.y = acc[i][5] + b1.y; o.z = acc[i][6] + b1.z; o.w = acc[i][7] + b1.w;
        *(float4*)(out + row * 128 + tx * 8 + 4) = o;
    }
}

// ---------------- launch -----------------------------------------------------
extern "C" void kernel_launch(void* const* d_in, const int* in_sizes, int n_in,
                              void* d_out, int out_size) {
    const float* x  = (const float*)d_in[0];
    const int*   ni = (const int*)d_in[1];
    const int*   hi = (const int*)d_in[2];
    const float* Wk = (const float*)d_in[3];
    const float* bk = (const float*)d_in[4];
    const float* Wq = (const float*)d_in[5];
    const float* bq = (const float*)d_in[6];
    const float* Wa = (const float*)d_in[7];
    const float* ba = (const float*)d_in[8];
    float* out = (float*)d_out;

    int* d_cnt_he; cudaGetSymbolAddress((void**)&d_cnt_he, g_cnt_he);
    int* d_cnt_n;  cudaGetSymbolAddress((void**)&d_cnt_n,  g_cnt_n);
    int* d_off_he; cudaGetSymbolAddress((void**)&d_off_he, g_off_he);
    int* d_off_n;  cudaGetSymbolAddress((void**)&d_off_n,  g_off_n);
    int* d_cur_he; cudaGetSymbolAddress((void**)&d_cur_he, g_cur_he);
    int* d_cur_n;  cudaGetSymbolAddress((void**)&d_cur_n,  g_cur_n);

    k_zero<<<(NN + 255) / 256, 256>>>();
    k_hist<<<(EE + 255) / 256, 256>>>(ni, hi);
    k_scan<<<1, 1024>>>(d_cnt_he, d_off_he, d_cur_he, NHE);
    k_scan<<<1, 1024>>>(d_cnt_n, d_off_n, d_cur_n, NN);
    k_scatter<<<(EE + 255) / 256, 256>>>(ni, hi);
    k_gemm_kq<<<(NN + 63) / 64, 256>>>(x, Wk, bk, Wq, bq);
    k_heagg<<<NHE * 32 / 256, 256>>>(0);
    k_attn<<<NN * 32 / 256, 256>>>(x);
    k_gemm_out<<<(NN + 63) / 64, 256>>>(Wa, ba, out);
}

// round 4
// speedup vs baseline: 1.3203x; 1.2705x over previous
#include <cuda_runtime.h>
#include <math_constants.h>

#define NN 100000
#define EE 1000000
#define NHE 20000
#define D 128
#define NHEAD 4
#define FULL 0xffffffffu

// ---------------- scratch (device globals: no allocation allowed) ------------
__device__ __align__(16) float g_hnode[NN * D];   // x@Wk+bk
__device__ __align__(16) float g_q[NN * D];       // x@Wq+bq
__device__ __align__(16) float g_hef[NHE * D];    // hyperedge features
__device__ __align__(16) float g_resid[NN * D];   // normalized attn out + x

__device__ int g_cnt_he[NHE], g_cnt_n[NN];
__device__ int g_off_he[NHE + 1], g_off_n[NN + 1];
__device__ int g_cur_he[NHE], g_cur_n[NN];
__device__ int g_he_nodes[EE];   // node ids grouped by hyperedge
__device__ int g_n_hes[EE];      // hyperedge ids grouped by node
__device__ int g_btot[128];      // block totals for hierarchical scan

// ---------------- CSR build --------------------------------------------------
__global__ void k_zero() {
    int i = blockIdx.x * 256 + threadIdx.x;
    if (i < NHE) g_cnt_he[i] = 0;
    if (i < NN) g_cnt_n[i] = 0;
}

__global__ void k_hist(const int* __restrict__ ni, const int* __restrict__ hi) {
    int e = blockIdx.x * 256 + threadIdx.x;
    if (e < EE) {
        atomicAdd(&g_cnt_he[__ldg(&hi[e])], 1);
        atomicAdd(&g_cnt_n[__ldg(&ni[e])], 1);
    }
}

// phase 1: per-block exclusive scan of 1024 counters (no base), block totals
__global__ void k_scan_blk(const int* __restrict__ cnt, int* __restrict__ off, int M) {
    __shared__ int sh[1024];
    int t = threadIdx.x;
    int i = blockIdx.x * 1024 + t;
    int v = (i < M) ? cnt[i] : 0;
    sh[t] = v;
    __syncthreads();
#pragma unroll
    for (int d = 1; d < 1024; d <<= 1) {
        int u = (t >= d) ? sh[t - d] : 0;
        __syncthreads();
        sh[t] += u;
        __syncthreads();
    }
    if (i < M) off[i] = sh[t] - v;               // exclusive within block
    if (t == 1023) g_btot[blockIdx.x] = sh[1023];
}

// phase 2: exclusive scan of block totals (B <= 128), one block of 128
__global__ void k_scan_top(int B) {
    __shared__ int sh[128];
    int t = threadIdx.x;
    int v = (t < B) ? g_btot[t] : 0;
    sh[t] = v;
    __syncthreads();
#pragma unroll
    for (int d = 1; d < 128; d <<= 1) {
        int u = (t >= d) ? sh[t - d] : 0;
        __syncthreads();
        sh[t] += u;
        __syncthreads();
    }
    if (t < B) g_btot[t] = sh[t] - v;            // exclusive
}

// phase 3: add block base; write cur=off; set off[M]=EE
__global__ void k_scan_add(int* __restrict__ off, int* __restrict__ cur, int M) {
    int i = blockIdx.x * 1024 + threadIdx.x;
    if (i < M) {
        int o = off[i] + g_btot[blockIdx.x];
        off[i] = o;
        cur[i] = o;
    }
    if (i == 0) off[M] = EE;
}

__global__ void k_scatter(const int* __restrict__ ni, const int* __restrict__ hi) {
    int e = blockIdx.x * 256 + threadIdx.x;
    if (e < EE) {
        int n = __ldg(&ni[e]), he = __ldg(&hi[e]);
        int p = atomicAdd(&g_cur_he[he], 1);
        g_he_nodes[p] = n;
        int p2 = atomicAdd(&g_cur_n[n], 1);
        g_n_hes[p2] = he;
    }
}

// ---------------- GEMM 1: h_node = x@Wk+bk, q = x@Wq+bq ----------------------
__global__ __launch_bounds__(256, 2) void k_gemm_kq(
    const float* __restrict__ x,
    const float* __restrict__ Wk, const float* __restrict__ bk,
    const float* __restrict__ Wq, const float* __restrict__ bq) {
    __shared__ __align__(16) float sA[64][33];
    __shared__ __align__(16) float sK[32][128];
    __shared__ __align__(16) float sQ[32][128];
    const int tid = threadIdx.x;
    const int tx = tid & 15, ty = tid >> 4;
    const int row0 = blockIdx.x * 64;

    float aK[4][8], aQ[4][8];
#pragma unroll
    for (int i = 0; i < 4; i++)
#pragma unroll
        for (int j = 0; j < 8; j++) { aK[i][j] = 0.f; aQ[i][j] = 0.f; }

    for (int kb = 0; kb < 4; kb++) {
#pragma unroll
        for (int t = 0; t < 2; t++) {
            int slot = tid * 2 + t;
            int r = slot >> 3;
            int c = (slot & 7) * 4;
            float4 v = make_float4(0.f, 0.f, 0.f, 0.f);
            int row = row0 + r;
            if (row < NN) v = *(const float4*)(x + row * 128 + kb * 32 + c);
            sA[r][c] = v.x; sA[r][c + 1] = v.y; sA[r][c + 2] = v.z; sA[r][c + 3] = v.w;
        }
#pragma unroll
        for (int t = 0; t < 4; t++) {
            int slot = tid * 4 + t;
            int r = slot >> 5;
            int c = (slot & 31) * 4;
            *(float4*)&sK[r][c] = *(const float4*)(Wk + (kb * 32 + r) * 128 + c);
            *(float4*)&sQ[r][c] = *(const float4*)(Wq + (kb * 32 + r) * 128 + c);
        }
        __syncthreads();
#pragma unroll 8
        for (int k = 0; k < 32; k++) {
            float a[4];
#pragma unroll
            for (int i = 0; i < 4; i++) a[i] = sA[ty * 4 + i][k];
            float4 k0 = *(float4*)&sK[k][tx * 8];
            float4 k1 = *(float4*)&sK[k][tx * 8 + 4];
            float4 q0 = *(float4*)&sQ[k][tx * 8];
            float4 q1 = *(float4*)&sQ[k][tx * 8 + 4];
#pragma unroll
            for (int i = 0; i < 4; i++) {
                aK[i][0] += a[i] * k0.x; aK[i][1] += a[i] * k0.y;
                aK[i][2] += a[i] * k0.z; aK[i][3] += a[i] * k0.w;
                aK[i][4] += a[i] * k1.x; aK[i][5] += a[i] * k1.y;
                aK[i][6] += a[i] * k1.z; aK[i][7] += a[i] * k1.w;
                aQ[i][0] += a[i] * q0.x; aQ[i][1] += a[i] * q0.y;
                aQ[i][2] += a[i] * q0.z; aQ[i][3] += a[i] * q0.w;
                aQ[i][4] += a[i] * q1.x; aQ[i][5] += a[i] * q1.y;
                aQ[i][6] += a[i] * q1.z; aQ[i][7] += a[i] * q1.w;
            }
        }
        __syncthreads();
    }
    float4 bk0 = *(const float4*)(bk + tx * 8), bk1 = *(const float4*)(bk + tx * 8 + 4);
    float4 bq0 = *(const float4*)(bq + tx * 8), bq1 = *(const float4*)(bq + tx * 8 + 4);
#pragma unroll
    for (int i = 0; i < 4; i++) {
        int row = row0 + ty * 4 + i;
        if (row >= NN) continue;
        float4 o;
        o.x = aK[i][0] + bk0.x; o.y = aK[i][1] + bk0.y; o.z = aK[i][2] + bk0.z; o.w = aK[i][3] + bk0.w;
        *(float4*)(g_hnode + row * 128 + tx * 8) = o;
        o.x = aK[i][4] + bk1.x; o.y = aK[i][5] + bk1.y; o.z = aK[i][6] + bk1.z; o.w = aK[i][7] + bk1.w;
        *(float4*)(g_hnode + row * 128 + tx * 8 + 4) = o;
        o.x = aQ[i][0] + bq0.x; o.y = aQ[i][1] + bq0.y; o.z = aQ[i][2] + bq0.z; o.w = aQ[i][3] + bq0.w;
        *(float4*)(g_q + row * 128 + tx * 8) = o;
        o.x = aQ[i][4] + bq1.x; o.y = aQ[i][5] + bq1.y; o.z = aQ[i][6] + bq1.z; o.w = aQ[i][7] + bq1.w;
        *(float4*)(g_q + row * 128 + tx * 8 + 4) = o;
    }
}

// ---------------- pass A: per-hyperedge aggregation (no atomics) -------------
__global__ void k_heagg(int dummy) {
    int g = blockIdx.x * 256 + threadIdx.x;
    int he = g >> 5, lane = g & 31;
    if (he >= NHE) return;
    int s = g_off_he[he], e = g_off_he[he + 1];
    float4 acc = make_float4(0.f, 0.f, 0.f, 0.f);
    int base = s;
    for (; base + 32 <= e; base += 32) {
        int myidx = __ldg(&g_he_nodes[base + lane]);
#pragma unroll
        for (int j = 0; j < 32; j += 4) {
            int n0 = __shfl_sync(FULL, myidx, j);
            int n1 = __shfl_sync(FULL, myidx, j + 1);
            int n2 = __shfl_sync(FULL, myidx, j + 2);
            int n3 = __shfl_sync(FULL, myidx, j + 3);
            float4 v0 = ((const float4*)g_hnode)[n0 * 32 + lane];
            float4 v1 = ((const float4*)g_hnode)[n1 * 32 + lane];
            float4 v2 = ((const float4*)g_hnode)[n2 * 32 + lane];
            float4 v3 = ((const float4*)g_hnode)[n3 * 32 + lane];
            acc.x += (v0.x + v1.x) + (v2.x + v3.x);
            acc.y += (v0.y + v1.y) + (v2.y + v3.y);
            acc.z += (v0.z + v1.z) + (v2.z + v3.z);
            acc.w += (v0.w + v1.w) + (v2.w + v3.w);
        }
    }
    if (base < e) {
        int cnt = e - base;
        int myidx = (lane < cnt) ? __ldg(&g_he_nodes[base + lane]) : 0;
        for (int j = 0; j < cnt; j++) {
            int node = __shfl_sync(FULL, myidx, j);
            float4 v = ((const float4*)g_hnode)[node * 32 + lane];
            acc.x += v.x; acc.y += v.y; acc.z += v.z; acc.w += v.w;
        }
    }
    ((float4*)g_hef)[he * 32 + lane] = acc;
}

// ---------------- fused pass B+C: per-node online-softmax attention ----------
__global__ void k_attn(const float* __restrict__ x) {
    int g = blockIdx.x * 256 + threadIdx.x;
    int n = g >> 5, lane = g & 31;
    if (n >= NN) return;
    float4 q4 = ((const float4*)g_q)[n * 32 + lane];
    int s = g_off_n[n], e = g_off_n[n + 1];
    float m = -CUDART_INF_F, ssum = 0.f;
    float4 acc = make_float4(0.f, 0.f, 0.f, 0.f);
    for (int base = s; base < e; base += 32) {
        int cnt = min(32, e - base);
        int myhe = (lane < cnt) ? __ldg(&g_n_hes[base + lane]) : 0;
#pragma unroll 2
        for (int j = 0; j < cnt; j++) {
            int he = __shfl_sync(FULL, myhe, j);
            float4 hv = ((const float4*)g_hef)[he * 32 + lane];
            float p = q4.x * hv.x + q4.y * hv.y + q4.z * hv.z + q4.w * hv.w;
            p += __shfl_xor_sync(FULL, p, 1);
            p += __shfl_xor_sync(FULL, p, 2);
            p += __shfl_xor_sync(FULL, p, 4);   // stays within 8-lane head group
            float alpha = p * 0.17677669529663687f;  // 1/sqrt(32)
            float mn = fmaxf(m, alpha);
            float c = __expf(m - mn);    // 0 on first iter (m=-inf)
            float ev = __expf(alpha - mn);
            ssum = ssum * c + ev;
            acc.x = acc.x * c + ev * hv.x;
            acc.y = acc.y * c + ev * hv.y;
            acc.z = acc.z * c + ev * hv.z;
            acc.w = acc.w * c + ev * hv.w;
            m = mn;
        }
    }
    float inv = 1.f / (ssum + 1e-16f);
    float4 xv = ((const float4*)x)[n * 32 + lane];
    float4 o;
    o.x = acc.x * inv + xv.x; o.y = acc.y * inv + xv.y;
    o.z = acc.z * inv + xv.z; o.w = acc.w * inv + xv.w;
    ((float4*)g_resid)[n * 32 + lane] = o;
}

// ---------------- final: out = g_resid @ Wa + ba -----------------------------
__global__ __launch_bounds__(256, 2) void k_gemm_out(
    const float* __restrict__ Wa, const float* __restrict__ ba,
    float* __restrict__ out) {
    __shared__ __align__(16) float sA[64][33];
    __shared__ __align__(16) float sW[32][128];
    const int tid = threadIdx.x;
    const int tx = tid & 15, ty = tid >> 4;
    const int row0 = blockIdx.x * 64;

    float acc[4][8];
#pragma unroll
    for (int i = 0; i < 4; i++)
#pragma unroll
        for (int j = 0; j < 8; j++) acc[i][j] = 0.f;

    for (int kb = 0; kb < 4; kb++) {
#pragma unroll
        for (int t = 0; t < 2; t++) {
            int slot = tid * 2 + t;
            int r = slot >> 3;
            int c = (slot & 7) * 4;
            float4 v = make_float4(0.f, 0.f, 0.f, 0.f);
            int row = row0 + r;
            if (row < NN) v = *(const float4*)(g_resid + row * 128 + kb * 32 + c);
            sA[r][c] = v.x; sA[r][c + 1] = v.y; sA[r][c + 2] = v.z; sA[r][c + 3] = v.w;
        }
#pragma unroll
        for (int t = 0; t < 4; t++) {
            int slot = tid * 4 + t;
            int r = slot >> 5;
            int c = (slot & 31) * 4;
            *(float4*)&sW[r][c] = *(const float4*)(Wa + (kb * 32 + r) * 128 + c);
        }
        __syncthreads();
#pragma unroll 8
        for (int k = 0; k < 32; k++) {
            float a[4];
#pragma unroll
            for (int i = 0; i < 4; i++) a[i] = sA[ty * 4 + i][k];
            float4 w0 = *(float4*)&sW[k][tx * 8];
            float4 w1 = *(float4*)&sW[k][tx * 8 + 4];
#pragma unroll
            for (int i = 0; i < 4; i++) {
                acc[i][0] += a[i] * w0.x; acc[i][1] += a[i] * w0.y;
                acc[i][2] += a[i] * w0.z; acc[i][3] += a[i] * w0.w;
                acc[i][4] += a[i] * w1.x; acc[i][5] += a[i] * w1.y;
                acc[i][6] += a[i] * w1.z; acc[i][7] += a[i] * w1.w;
            }
        }
        __syncthreads();
    }
    float4 b0 = *(const float4*)(ba + tx * 8), b1 = *(const float4*)(ba + tx * 8 + 4);
#pragma unroll
    for (int i = 0; i < 4; i++) {
        int row = row0 + ty * 4 + i;
        if (row >= NN) continue;
        float4 o;
        o.x = acc[i][0] + b0.x; o.y = acc[i][1] + b0.y; o.z = acc[i][2] + b0.z; o.w = acc[i][3] + b0.w;
        *(float4*)(out + row * 128 + tx * 8) = o;
        o.x = acc[i][4] + b1.x; o.y = acc[i][5] + b1.y; o.z = acc[i][6] + b1.z; o.w = acc[i][7] + b1.w;
        *(float4*)(out + row * 128 + tx * 8 + 4) = o;
    }
}

// ---------------- launch -----------------------------------------------------
extern "C" void kernel_launch(void* const* d_in, const int* in_sizes, int n_in,
                              void* d_out, int out_size) {
    const float* x  = (const float*)d_in[0];
    const int*   ni = (const int*)d_in[1];
    const int*   hi = (const int*)d_in[2];
    const float* Wk = (const float*)d_in[3];
    const float* bk = (const float*)d_in[4];
    const float* Wq = (const float*)d_in[5];
    const float* bq = (const float*)d_in[6];
    const float* Wa = (const float*)d_in[7];
    const float* ba = (const float*)d_in[8];
    float* out = (float*)d_out;

    int* d_cnt_he; cudaGetSymbolAddress((void**)&d_cnt_he, g_cnt_he);
    int* d_cnt_n;  cudaGetSymbolAddress((void**)&d_cnt_n,  g_cnt_n);
    int* d_off_he; cudaGetSymbolAddress((void**)&d_off_he, g_off_he);
    int* d_off_n;  cudaGetSymbolAddress((void**)&d_off_n,  g_off_n);
    int* d_cur_he; cudaGetSymbolAddress((void**)&d_cur_he, g_cur_he);
    int* d_cur_n;  cudaGetSymbolAddress((void**)&d_cur_n,  g_cur_n);

    const int B_HE = (NHE + 1023) / 1024;   // 20
    const int B_N  = (NN + 1023) / 1024;    // 98

    k_zero<<<(NN + 255) / 256, 256>>>();
    k_hist<<<(EE + 255) / 256, 256>>>(ni, hi);
    // hierarchical scan: hyperedge counters
    k_scan_blk<<<B_HE, 1024>>>(d_cnt_he, d_off_he, NHE);
    k_scan_top<<<1, 128>>>(B_HE);
    k_scan_add<<<B_HE, 1024>>>(d_off_he, d_cur_he, NHE);
    // hierarchical scan: node counters
    k_scan_blk<<<B_N, 1024>>>(d_cnt_n, d_off_n, NN);
    k_scan_top<<<1, 128>>>(B_N);
    k_scan_add<<<B_N, 1024>>>(d_off_n, d_cur_n, NN);

    k_scatter<<<(EE + 255) / 256, 256>>>(ni, hi);
    k_gemm_kq<<<(NN + 63) / 64, 256>>>(x, Wk, bk, Wq, bq);
    k_heagg<<<NHE * 32 / 256, 256>>>(0);
    k_attn<<<NN * 32 / 256, 256>>>(x);
    k_gemm_out<<<(NN + 63) / 64, 256>>>(Wa, ba, out);
}

// round 6
// speedup vs baseline: 1.4147x; 1.0715x over previous
#include <cuda_runtime.h>
#include <math_constants.h>

#define NN 100000
#define EE 1000000
#define NHE 20000
#define D 128
#define NHEAD 4
#define FULL 0xffffffffu

// ---------------- scratch (device globals: no allocation allowed) ------------
__device__ __align__(16) float g_hnode[NN * D];   // x@Wk+bk
__device__ __align__(16) float g_q[NN * D];       // x@Wq+bq
__device__ __align__(16) float g_hef[NHE * D];    // hyperedge features
__device__ __align__(16) float g_resid[NN * D];   // normalized attn out + x

__device__ int g_cnt_he[NHE], g_cnt_n[NN];
__device__ int g_off_he[NHE + 1], g_off_n[NN + 1];
__device__ int g_cur_he[NHE], g_cur_n[NN];
__device__ int g_he_nodes[EE];   // node ids grouped by hyperedge
__device__ int g_n_hes[EE];      // hyperedge ids grouped by node
__device__ int g_btot[128];      // block totals for hierarchical scan

// ---------------- CSR build --------------------------------------------------
__global__ void k_zero() {
    int i = blockIdx.x * 256 + threadIdx.x;
    if (i < NHE) g_cnt_he[i] = 0;
    if (i < NN) g_cnt_n[i] = 0;
}

__global__ void k_hist(const int* __restrict__ ni, const int* __restrict__ hi) {
    int e = blockIdx.x * 256 + threadIdx.x;
    if (e < EE) {
        atomicAdd(&g_cnt_he[__ldg(&hi[e])], 1);
        atomicAdd(&g_cnt_n[__ldg(&ni[e])], 1);
    }
}

// phase 1: per-block exclusive scan of 1024 counters (no base), block totals
__global__ void k_scan_blk(const int* __restrict__ cnt, int* __restrict__ off, int M) {
    __shared__ int sh[1024];
    int t = threadIdx.x;
    int i = blockIdx.x * 1024 + t;
    int v = (i < M) ? cnt[i] : 0;
    sh[t] = v;
    __syncthreads();
#pragma unroll
    for (int d = 1; d < 1024; d <<= 1) {
        int u = (t >= d) ? sh[t - d] : 0;
        __syncthreads();
        sh[t] += u;
        __syncthreads();
    }
    if (i < M) off[i] = sh[t] - v;               // exclusive within block
    if (t == 1023) g_btot[blockIdx.x] = sh[1023];
}

// phase 2: exclusive scan of block totals (B <= 128), one block of 128
__global__ void k_scan_top(int B) {
    __shared__ int sh[128];
    int t = threadIdx.x;
    int v = (t < B) ? g_btot[t] : 0;
    sh[t] = v;
    __syncthreads();
#pragma unroll
    for (int d = 1; d < 128; d <<= 1) {
        int u = (t >= d) ? sh[t - d] : 0;
        __syncthreads();
        sh[t] += u;
        __syncthreads();
    }
    if (t < B) g_btot[t] = sh[t] - v;            // exclusive
}

// phase 3: add block base; write cur=off; set off[M]=EE
__global__ void k_scan_add(int* __restrict__ off, int* __restrict__ cur, int M) {
    int i = blockIdx.x * 1024 + threadIdx.x;
    if (i < M) {
        int o = off[i] + g_btot[blockIdx.x];
        off[i] = o;
        cur[i] = o;
    }
    if (i == 0) off[M] = EE;
}

__global__ void k_scatter(const int* __restrict__ ni, const int* __restrict__ hi) {
    int e = blockIdx.x * 256 + threadIdx.x;
    if (e < EE) {
        int n = __ldg(&ni[e]), he = __ldg(&hi[e]);
        int p = atomicAdd(&g_cur_he[he], 1);
        g_he_nodes[p] = n;
        int p2 = atomicAdd(&g_cur_n[n], 1);
        g_n_hes[p2] = he;
    }
}

// ---------------- GEMM 1: h_node = x@Wk+bk, q = x@Wq+bq ----------------------
__global__ __launch_bounds__(256, 2) void k_gemm_kq(
    const float* __restrict__ x,
    const float* __restrict__ Wk, const float* __restrict__ bk,
    const float* __restrict__ Wq, const float* __restrict__ bq) {
    __shared__ __align__(16) float sA[64][33];
    __shared__ __align__(16) float sK[32][128];
    __shared__ __align__(16) float sQ[32][128];
    const int tid = threadIdx.x;
    const int tx = tid & 15, ty = tid >> 4;
    const int row0 = blockIdx.x * 64;

    float aK[4][8], aQ[4][8];
#pragma unroll
    for (int i = 0; i < 4; i++)
#pragma unroll
        for (int j = 0; j < 8; j++) { aK[i][j] = 0.f; aQ[i][j] = 0.f; }

    for (int kb = 0; kb < 4; kb++) {
#pragma unroll
        for (int t = 0; t < 2; t++) {
            int slot = tid * 2 + t;
            int r = slot >> 3;
            int c = (slot & 7) * 4;
            float4 v = make_float4(0.f, 0.f, 0.f, 0.f);
            int row = row0 + r;
            if (row < NN) v = *(const float4*)(x + row * 128 + kb * 32 + c);
            sA[r][c] = v.x; sA[r][c + 1] = v.y; sA[r][c + 2] = v.z; sA[r][c + 3] = v.w;
        }
#pragma unroll
        for (int t = 0; t < 4; t++) {
            int slot = tid * 4 + t;
            int r = slot >> 5;
            int c = (slot & 31) * 4;
            *(float4*)&sK[r][c] = *(const float4*)(Wk + (kb * 32 + r) * 128 + c);
            *(float4*)&sQ[r][c] = *(const float4*)(Wq + (kb * 32 + r) * 128 + c);
        }
        __syncthreads();
#pragma unroll 8
        for (int k = 0; k < 32; k++) {
            float a[4];
#pragma unroll
            for (int i = 0; i < 4; i++) a[i] = sA[ty * 4 + i][k];
            float4 k0 = *(float4*)&sK[k][tx * 8];
            float4 k1 = *(float4*)&sK[k][tx * 8 + 4];
            float4 q0 = *(float4*)&sQ[k][tx * 8];
            float4 q1 = *(float4*)&sQ[k][tx * 8 + 4];
#pragma unroll
            for (int i = 0; i < 4; i++) {
                aK[i][0] += a[i] * k0.x; aK[i][1] += a[i] * k0.y;
                aK[i][2] += a[i] * k0.z; aK[i][3] += a[i] * k0.w;
                aK[i][4] += a[i] * k1.x; aK[i][5] += a[i] * k1.y;
                aK[i][6] += a[i] * k1.z; aK[i][7] += a[i] * k1.w;
                aQ[i][0] += a[i] * q0.x; aQ[i][1] += a[i] * q0.y;
                aQ[i][2] += a[i] * q0.z; aQ[i][3] += a[i] * q0.w;
                aQ[i][4] += a[i] * q1.x; aQ[i][5] += a[i] * q1.y;
                aQ[i][6] += a[i] * q1.z; aQ[i][7] += a[i] * q1.w;
            }
        }
        __syncthreads();
    }
    float4 bk0 = *(const float4*)(bk + tx * 8), bk1 = *(const float4*)(bk + tx * 8 + 4);
    float4 bq0 = *(const float4*)(bq + tx * 8), bq1 = *(const float4*)(bq + tx * 8 + 4);
#pragma unroll
    for (int i = 0; i < 4; i++) {
        int row = row0 + ty * 4 + i;
        if (row >= NN) continue;
        float4 o;
        o.x = aK[i][0] + bk0.x; o.y = aK[i][1] + bk0.y; o.z = aK[i][2] + bk0.z; o.w = aK[i][3] + bk0.w;
        *(float4*)(g_hnode + row * 128 + tx * 8) = o;
        o.x = aK[i][4] + bk1.x; o.y = aK[i][5] + bk1.y; o.z = aK[i][6] + bk1.z; o.w = aK[i][7] + bk1.w;
        *(float4*)(g_hnode + row * 128 + tx * 8 + 4) = o;
        o.x = aQ[i][0] + bq0.x; o.y = aQ[i][1] + bq0.y; o.z = aQ[i][2] + bq0.z; o.w = aQ[i][3] + bq0.w;
        *(float4*)(g_q + row * 128 + tx * 8) = o;
        o.x = aQ[i][4] + bq1.x; o.y = aQ[i][5] + bq1.y; o.z = aQ[i][6] + bq1.z; o.w = aQ[i][7] + bq1.w;
        *(float4*)(g_q + row * 128 + tx * 8 + 4) = o;
    }
}

// ---------------- pass A: per-hyperedge aggregation (no atomics) -------------
__global__ void k_heagg(int dummy) {
    int g = blockIdx.x * 256 + threadIdx.x;
    int he = g >> 5, lane = g & 31;
    if (he >= NHE) return;
    int s = g_off_he[he], e = g_off_he[he + 1];
    float4 acc = make_float4(0.f, 0.f, 0.f, 0.f);
    int base = s;
    for (; base + 32 <= e; base += 32) {
        int myidx = __ldg(&g_he_nodes[base + lane]);
#pragma unroll
        for (int j = 0; j < 32; j += 4) {
            int n0 = __shfl_sync(FULL, myidx, j);
            int n1 = __shfl_sync(FULL, myidx, j + 1);
            int n2 = __shfl_sync(FULL, myidx, j + 2);
            int n3 = __shfl_sync(FULL, myidx, j + 3);
            float4 v0 = ((const float4*)g_hnode)[n0 * 32 + lane];
            float4 v1 = ((const float4*)g_hnode)[n1 * 32 + lane];
            float4 v2 = ((const float4*)g_hnode)[n2 * 32 + lane];
            float4 v3 = ((const float4*)g_hnode)[n3 * 32 + lane];
            acc.x += (v0.x + v1.x) + (v2.x + v3.x);
            acc.y += (v0.y + v1.y) + (v2.y + v3.y);
            acc.z += (v0.z + v1.z) + (v2.z + v3.z);
            acc.w += (v0.w + v1.w) + (v2.w + v3.w);
        }
    }
    if (base < e) {
        int cnt = e - base;
        int myidx = (lane < cnt) ? __ldg(&g_he_nodes[base + lane]) : 0;
        for (int j = 0; j < cnt; j++) {
            int node = __shfl_sync(FULL, myidx, j);
            float4 v = ((const float4*)g_hnode)[node * 32 + lane];
            acc.x += v.x; acc.y += v.y; acc.z += v.z; acc.w += v.w;
        }
    }
    ((float4*)g_hef)[he * 32 + lane] = acc;
}

// ---------------- fused pass B+C: per-node online-softmax attention ----------
// software-pipelined: prefetch edge j+1's he_feat row while processing edge j
__global__ void k_attn(const float* __restrict__ x) {
    int g = blockIdx.x * 256 + threadIdx.x;
    int n = g >> 5, lane = g & 31;
    if (n >= NN) return;
    float4 q4 = ((const float4*)g_q)[n * 32 + lane];
    int s = g_off_n[n], e = g_off_n[n + 1];
    float m = -CUDART_INF_F, ssum = 0.f;
    float4 acc = make_float4(0.f, 0.f, 0.f, 0.f);
    for (int base = s; base < e; base += 32) {
        int cnt = min(32, e - base);
        int myhe = (lane < cnt) ? __ldg(&g_n_hes[base + lane]) : 0;
        int he0 = __shfl_sync(FULL, myhe, 0);
        float4 hv = ((const float4*)g_hef)[he0 * 32 + lane];
        for (int j = 0; j < cnt; j++) {
            float4 cur = hv;
            if (j + 1 < cnt) {
                int hen = __shfl_sync(FULL, myhe, j + 1);
                hv = ((const float4*)g_hef)[hen * 32 + lane];
            }
            float p = q4.x * cur.x + q4.y * cur.y + q4.z * cur.z + q4.w * cur.w;
            p += __shfl_xor_sync(FULL, p, 1);
            p += __shfl_xor_sync(FULL, p, 2);
            p += __shfl_xor_sync(FULL, p, 4);   // stays within 8-lane head group
            float alpha = p * 0.17677669529663687f;  // 1/sqrt(32)
            float mn = fmaxf(m, alpha);
            float c = __expf(m - mn);    // 0 on first iter (m=-inf)
            float ev = __expf(alpha - mn);
            ssum = ssum * c + ev;
            acc.x = acc.x * c + ev * cur.x;
            acc.y = acc.y * c + ev * cur.y;
            acc.z = acc.z * c + ev * cur.z;
            acc.w = acc.w * c + ev * cur.w;
            m = mn;
        }
    }
    float inv = 1.f / (ssum + 1e-16f);
    float4 xv = ((const float4*)x)[n * 32 + lane];
    float4 o;
    o.x = acc.x * inv + xv.x; o.y = acc.y * inv + xv.y;
    o.z = acc.z * inv + xv.z; o.w = acc.w * inv + xv.w;
    ((float4*)g_resid)[n * 32 + lane] = o;
}

// ---------------- final: out = g_resid @ Wa + ba -----------------------------
__global__ __launch_bounds__(256, 2) void k_gemm_out(
    const float* __restrict__ Wa, const float* __restrict__ ba,
    float* __restrict__ out) {
    __shared__ __align__(16) float sA[64][33];
    __shared__ __align__(16) float sW[32][128];
    const int tid = threadIdx.x;
    const int tx = tid & 15, ty = tid >> 4;
    const int row0 = blockIdx.x * 64;

    float acc[4][8];
#pragma unroll
    for (int i = 0; i < 4; i++)
#pragma unroll
        for (int j = 0; j < 8; j++) acc[i][j] = 0.f;

    for (int kb = 0; kb < 4; kb++) {
#pragma unroll
        for (int t = 0; t < 2; t++) {
            int slot = tid * 2 + t;
            int r = slot >> 3;
            int c = (slot & 7) * 4;
            float4 v = make_float4(0.f, 0.f, 0.f, 0.f);
            int row = row0 + r;
            if (row < NN) v = *(const float4*)(g_resid + row * 128 + kb * 32 + c);
            sA[r][c] = v.x; sA[r][c + 1] = v.y; sA[r][c + 2] = v.z; sA[r][c + 3] = v.w;
        }
#pragma unroll
        for (int t = 0; t < 4; t++) {
            int slot = tid * 4 + t;
            int r = slot >> 5;
            int c = (slot & 31) * 4;
            *(float4*)&sW[r][c] = *(const float4*)(Wa + (kb * 32 + r) * 128 + c);
        }
        __syncthreads();
#pragma unroll 8
        for (int k = 0; k < 32; k++) {
            float a[4];
#pragma unroll
            for (int i = 0; i < 4; i++) a[i] = sA[ty * 4 + i][k];
            float4 w0 = *(float4*)&sW[k][tx * 8];
            float4 w1 = *(float4*)&sW[k][tx * 8 + 4];
#pragma unroll
            for (int i = 0; i < 4; i++) {
                acc[i][0] += a[i] * w0.x; acc[i][1] += a[i] * w0.y;
                acc[i][2] += a[i] * w0.z; acc[i][3] += a[i] * w0.w;
                acc[i][4] += a[i] * w1.x; acc[i][5] += a[i] * w1.y;
                acc[i][6] += a[i] * w1.z; acc[i][7] += a[i] * w1.w;
            }
        }
        __syncthreads();
    }
    float4 b0 = *(const float4*)(ba + tx * 8), b1 = *(const float4*)(ba + tx * 8 + 4);
#pragma unroll
    for (int i = 0; i < 4; i++) {
        int row = row0 + ty * 4 + i;
        if (row >= NN) continue;
        float4 o;
        o.x = acc[i][0] + b0.x; o.y = acc[i][1] + b0.y; o.z = acc[i][2] + b0.z; o.w = acc[i][3] + b0.w;
        *(float4*)(out + row * 128 + tx * 8) = o;
        o.x = acc[i][4] + b1.x; o.y = acc[i][5] + b1.y; o.z = acc[i][6] + b1.z; o.w = acc[i][7] + b1.w;
        *(float4*)(out + row * 128 + tx * 8 + 4) = o;
    }
}

// ---------------- launch -----------------------------------------------------
extern "C" void kernel_launch(void* const* d_in, const int* in_sizes, int n_in,
                              void* d_out, int out_size) {
    const float* x  = (const float*)d_in[0];
    const int*   ni = (const int*)d_in[1];
    const int*   hi = (const int*)d_in[2];
    const float* Wk = (const float*)d_in[3];
    const float* bk = (const float*)d_in[4];
    const float* Wq = (const float*)d_in[5];
    const float* bq = (const float*)d_in[6];
    const float* Wa = (const float*)d_in[7];
    const float* ba = (const float*)d_in[8];
    float* out = (float*)d_out;

    int* d_cnt_he; cudaGetSymbolAddress((void**)&d_cnt_he, g_cnt_he);
    int* d_cnt_n;  cudaGetSymbolAddress((void**)&d_cnt_n,  g_cnt_n);
    int* d_off_he; cudaGetSymbolAddress((void**)&d_off_he, g_off_he);
    int* d_off_n;  cudaGetSymbolAddress((void**)&d_off_n,  g_off_n);
    int* d_cur_he; cudaGetSymbolAddress((void**)&d_cur_he, g_cur_he);
    int* d_cur_n;  cudaGetSymbolAddress((void**)&d_cur_n,  g_cur_n);

    const int B_HE = (NHE + 1023) / 1024;   // 20
    const int B_N  = (NN + 1023) / 1024;    // 98

    // lazy-init side stream + fork/join events (no per-call create/destroy)
    static cudaStream_t s1 = nullptr;
    static cudaEvent_t evFork = nullptr, evJoin = nullptr;
    if (!s1) {
        cudaStreamCreateWithFlags(&s1, cudaStreamNonBlocking);
        cudaEventCreateWithFlags(&evFork, cudaEventDisableTiming);
        cudaEventCreateWithFlags(&evJoin, cudaEventDisableTiming);
    }

    // fork: CSR build on side stream, KQ GEMM on main stream (independent)
    cudaEventRecord(evFork, 0);
    cudaStreamWaitEvent(s1, evFork, 0);

    // side stream: CSR build
    k_zero<<<(NN + 255) / 256, 256, 0, s1>>>();
    k_hist<<<(EE + 255) / 256, 256, 0, s1>>>(ni, hi);
    k_scan_blk<<<B_HE, 1024, 0, s1>>>(d_cnt_he, d_off_he, NHE);
    k_scan_top<<<1, 128, 0, s1>>>(B_HE);
    k_scan_add<<<B_HE, 1024, 0, s1>>>(d_off_he, d_cur_he, NHE);
    k_scan_blk<<<B_N, 1024, 0, s1>>>(d_cnt_n, d_off_n, NN);
    k_scan_top<<<1, 128, 0, s1>>>(B_N);
    k_scan_add<<<B_N, 1024, 0, s1>>>(d_off_n, d_cur_n, NN);
    k_scatter<<<(EE + 255) / 256, 256, 0, s1>>>(ni, hi);
    cudaEventRecord(evJoin, s1);

    // main stream: dense KQ GEMM (concurrent with CSR build)
    k_gemm_kq<<<(NN + 63) / 64, 256>>>(x, Wk, bk, Wq, bq);

    // join, then the dependent tail
    cudaStreamWaitEvent(0, evJoin, 0);
    k_heagg<<<NHE * 32 / 256, 256>>>(0);
    k_attn<<<NN * 32 / 256, 256>>>(x);
    k_gemm_out<<<(NN + 63) / 64, 256>>>(Wa, ba, out);
}

// round 7
// speedup vs baseline: 2.5808x; 1.8242x over previous
#include <cuda_runtime.h>
#include <math_constants.h>
#include <cstdint>

#define NN 100000
#define EE 1000000
#define NHE 20000
#define D 128
#define FULL 0xffffffffu

// ---------------- scratch (device globals: no allocation allowed) ------------
__device__ __align__(16) float g_hnode[NN * D];   // x@Wk+bk
__device__ __align__(16) float g_q[NN * D];       // x@Wq+bq
__device__ __align__(16) float g_hef[NHE * D];    // hyperedge features
__device__ __align__(16) float g_resid[NN * D];   // normalized attn out + x

__device__ int g_cnt_he[NHE], g_cnt_n[NN];
__device__ int g_off_he[NHE + 1], g_off_n[NN + 1];
__device__ int g_cur_he[NHE], g_cur_n[NN];
__device__ int g_he_nodes[EE];   // node ids grouped by hyperedge
__device__ int g_n_hes[EE];      // hyperedge ids grouped by node
__device__ int g_btot[128];      // block totals for hierarchical scan

// ---------------- CSR build --------------------------------------------------
__global__ void k_zero() {
    int i = blockIdx.x * 256 + threadIdx.x;
    if (i < NHE) g_cnt_he[i] = 0;
    if (i < NN) g_cnt_n[i] = 0;
}

__global__ void k_hist(const int* __restrict__ ni, const int* __restrict__ hi) {
    int e = blockIdx.x * 256 + threadIdx.x;
    if (e < EE) {
        atomicAdd(&g_cnt_he[__ldg(&hi[e])], 1);
        atomicAdd(&g_cnt_n[__ldg(&ni[e])], 1);
    }
}

__global__ void k_scan_blk(const int* __restrict__ cnt, int* __restrict__ off, int M) {
    __shared__ int sh[1024];
    int t = threadIdx.x;
    int i = blockIdx.x * 1024 + t;
    int v = (i < M) ? cnt[i] : 0;
    sh[t] = v;
    __syncthreads();
#pragma unroll
    for (int d = 1; d < 1024; d <<= 1) {
        int u = (t >= d) ? sh[t - d] : 0;
        __syncthreads();
        sh[t] += u;
        __syncthreads();
    }
    if (i < M) off[i] = sh[t] - v;
    if (t == 1023) g_btot[blockIdx.x] = sh[1023];
}

__global__ void k_scan_top(int B) {
    __shared__ int sh[128];
    int t = threadIdx.x;
    int v = (t < B) ? g_btot[t] : 0;
    sh[t] = v;
    __syncthreads();
#pragma unroll
    for (int d = 1; d < 128; d <<= 1) {
        int u = (t >= d) ? sh[t - d] : 0;
        __syncthreads();
        sh[t] += u;
        __syncthreads();
    }
    if (t < B) g_btot[t] = sh[t] - v;
}

__global__ void k_scan_add(int* __restrict__ off, int* __restrict__ cur, int M) {
    int i = blockIdx.x * 1024 + threadIdx.x;
    if (i < M) {
        int o = off[i] + g_btot[blockIdx.x];
        off[i] = o;
        cur[i] = o;
    }
    if (i == 0) off[M] = EE;
}

__global__ void k_scatter_he(const int* __restrict__ ni, const int* __restrict__ hi) {
    int e = blockIdx.x * 256 + threadIdx.x;
    if (e < EE) {
        int p = atomicAdd(&g_cur_he[__ldg(&hi[e])], 1);
        g_he_nodes[p] = __ldg(&ni[e]);
    }
}

__global__ void k_scatter_n(const int* __restrict__ ni, const int* __restrict__ hi) {
    int e = blockIdx.x * 256 + threadIdx.x;
    if (e < EE) {
        int p = atomicAdd(&g_cur_n[__ldg(&ni[e])], 1);
        g_n_hes[p] = __ldg(&hi[e]);
    }
}

// ---------------- TF32 tensor-core GEMM: Out = A @ W + bias ------------------
// A [NN x 128] row-major, W [128 x 128] row-major (in,out), bias [128]
__device__ __forceinline__ uint32_t f2tf(float f) {
    uint32_t r;
    asm("cvt.rna.tf32.f32 %0, %1;" : "=r"(r) : "f"(f));
    return r;
}

__global__ __launch_bounds__(256, 2) void k_gemm_tf32(
    const float* __restrict__ A, const float* __restrict__ W,
    const float* __restrict__ bias, float* __restrict__ Out) {
    __shared__ uint32_t sA[128][36];    // 128 rows x 32 k (tf32 bits), pad 36
    __shared__ uint32_t sW[32][136];    // 32 k x 128 n, pad 136 (conflict-free frags)
    const int tid = threadIdx.x;
    const int lane = tid & 31, wid = tid >> 5;
    const int row0 = blockIdx.x * 128;
    const int wrow = wid * 16;           // warp's 16-row slice
    const int gr = lane >> 2, tg = lane & 3;

    float acc[16][4];
#pragma unroll
    for (int i = 0; i < 16; i++)
#pragma unroll
        for (int j = 0; j < 4; j++) acc[i][j] = 0.f;

    for (int kb = 0; kb < 4; kb++) {     // K chunks of 32
        // stage A chunk (convert to tf32 bits)
#pragma unroll
        for (int i = 0; i < 4; i++) {
            int slot = i * 256 + tid;            // 1024 float4 slots
            int r = slot >> 3, c4 = (slot & 7) * 4;
            float4 v = make_float4(0.f, 0.f, 0.f, 0.f);
            if (row0 + r < NN) v = *(const float4*)(A + (size_t)(row0 + r) * 128 + kb * 32 + c4);
            uint4 u = make_uint4(f2tf(v.x), f2tf(v.y), f2tf(v.z), f2tf(v.w));
            *(uint4*)&sA[r][c4] = u;
        }
        // stage W chunk
#pragma unroll
        for (int i = 0; i < 4; i++) {
            int slot = i * 256 + tid;            // 1024 float4 slots
            int r = slot >> 5, c4 = (slot & 31) * 4;
            float4 v = *(const float4*)(W + (size_t)(kb * 32 + r) * 128 + c4);
            uint4 u = make_uint4(f2tf(v.x), f2tf(v.y), f2tf(v.z), f2tf(v.w));
            *(uint4*)&sW[r][c4] = u;
        }
        __syncthreads();

#pragma unroll
        for (int ks = 0; ks < 4; ks++) {         // 4 x k8 steps per chunk
            int k0 = ks * 8;
            uint32_t a0 = sA[wrow + gr][k0 + tg];
            uint32_t a1 = sA[wrow + gr + 8][k0 + tg];
            uint32_t a2 = sA[wrow + gr][k0 + tg + 4];
            uint32_t a3 = sA[wrow + gr + 8][k0 + tg + 4];
#pragma unroll
            for (int nt = 0; nt < 16; nt++) {
                uint32_t b0 = sW[k0 + tg][nt * 8 + gr];
                uint32_t b1 = sW[k0 + tg + 4][nt * 8 + gr];
                asm volatile(
                    "mma.sync.aligned.m16n8k8.row.col.f32.tf32.tf32.f32 "
                    "{%0,%1,%2,%3}, {%4,%5,%6,%7}, {%8,%9}, {%0,%1,%2,%3};"
                    : "+f"(acc[nt][0]), "+f"(acc[nt][1]),
                      "+f"(acc[nt][2]), "+f"(acc[nt][3])
                    : "r"(a0), "r"(a1), "r"(a2), "r"(a3), "r"(b0), "r"(b1));
            }
        }
        __syncthreads();
    }

    // epilogue: add bias, write
    int r1 = row0 + wrow + gr, r2 = r1 + 8;
#pragma unroll
    for (int nt = 0; nt < 16; nt++) {
        int n = nt * 8 + tg * 2;
        float b0v = __ldg(&bias[n]), b1v = __ldg(&bias[n + 1]);
        if (r1 < NN) {
            Out[(size_t)r1 * 128 + n]     = acc[nt][0] + b0v;
            Out[(size_t)r1 * 128 + n + 1] = acc[nt][1] + b1v;
        }
        if (r2 < NN) {
            Out[(size_t)r2 * 128 + n]     = acc[nt][2] + b0v;
            Out[(size_t)r2 * 128 + n + 1] = acc[nt][3] + b1v;
        }
    }
}

// ---------------- pass A: per-hyperedge aggregation (no atomics) -------------
__global__ void k_heagg() {
    int g = blockIdx.x * 256 + threadIdx.x;
    int he = g >> 5, lane = g & 31;
    if (he >= NHE) return;
    int s = g_off_he[he], e = g_off_he[he + 1];
    float4 acc = make_float4(0.f, 0.f, 0.f, 0.f);
    int base = s;
    for (; base + 32 <= e; base += 32) {
        int myidx = __ldg(&g_he_nodes[base + lane]);
#pragma unroll
        for (int j = 0; j < 32; j += 4) {
            int n0 = __shfl_sync(FULL, myidx, j);
            int n1 = __shfl_sync(FULL, myidx, j + 1);
            int n2 = __shfl_sync(FULL, myidx, j + 2);
            int n3 = __shfl_sync(FULL, myidx, j + 3);
            float4 v0 = ((const float4*)g_hnode)[n0 * 32 + lane];
            float4 v1 = ((const float4*)g_hnode)[n1 * 32 + lane];
            float4 v2 = ((const float4*)g_hnode)[n2 * 32 + lane];
            float4 v3 = ((const float4*)g_hnode)[n3 * 32 + lane];
            acc.x += (v0.x + v1.x) + (v2.x + v3.x);
            acc.y += (v0.y + v1.y) + (v2.y + v3.y);
            acc.z += (v0.z + v1.z) + (v2.z + v3.z);
            acc.w += (v0.w + v1.w) + (v2.w + v3.w);
        }
    }
    if (base < e) {
        int cnt = e - base;
        int myidx = (lane < cnt) ? __ldg(&g_he_nodes[base + lane]) : 0;
        for (int j = 0; j < cnt; j++) {
            int node = __shfl_sync(FULL, myidx, j);
            float4 v = ((const float4*)g_hnode)[node * 32 + lane];
            acc.x += v.x; acc.y += v.y; acc.z += v.z; acc.w += v.w;
        }
    }
    ((float4*)g_hef)[he * 32 + lane] = acc;
}

// ---------------- fused pass B+C: per-node online-softmax attention ----------
__global__ void k_attn(const float* __restrict__ x) {
    int g = blockIdx.x * 256 + threadIdx.x;
    int n = g >> 5, lane = g & 31;
    if (n >= NN) return;
    float4 q4 = ((const float4*)g_q)[n * 32 + lane];
    int s = g_off_n[n], e = g_off_n[n + 1];
    float m = -CUDART_INF_F, ssum = 0.f;
    float4 acc = make_float4(0.f, 0.f, 0.f, 0.f);
    for (int base = s; base < e; base += 32) {
        int cnt = min(32, e - base);
        int myhe = (lane < cnt) ? __ldg(&g_n_hes[base + lane]) : 0;
        int he0 = __shfl_sync(FULL, myhe, 0);
        float4 hv = ((const float4*)g_hef)[he0 * 32 + lane];
        for (int j = 0; j < cnt; j++) {
            float4 cur = hv;
            if (j + 1 < cnt) {
                int hen = __shfl_sync(FULL, myhe, j + 1);
                hv = ((const float4*)g_hef)[hen * 32 + lane];
            }
            float p = q4.x * cur.x + q4.y * cur.y + q4.z * cur.z + q4.w * cur.w;
            p += __shfl_xor_sync(FULL, p, 1);
            p += __shfl_xor_sync(FULL, p, 2);
            p += __shfl_xor_sync(FULL, p, 4);   // within 8-lane head group
            float alpha = p * 0.17677669529663687f;  // 1/sqrt(32)
            float mn = fmaxf(m, alpha);
            float c = __expf(m - mn);
            float ev = __expf(alpha - mn);
            ssum = ssum * c + ev;
            acc.x = acc.x * c + ev * cur.x;
            acc.y = acc.y * c + ev * cur.y;
            acc.z = acc.z * c + ev * cur.z;
            acc.w = acc.w * c + ev * cur.w;
            m = mn;
        }
    }
    float inv = 1.f / (ssum + 1e-16f);
    float4 xv = ((const float4*)x)[n * 32 + lane];
    float4 o;
    o.x = acc.x * inv + xv.x; o.y = acc.y * inv + xv.y;
    o.z = acc.z * inv + xv.z; o.w = acc.w * inv + xv.w;
    ((float4*)g_resid)[n * 32 + lane] = o;
}

// ---------------- launch -----------------------------------------------------
extern "C" void kernel_launch(void* const* d_in, const int* in_sizes, int n_in,
                              void* d_out, int out_size) {
    const float* x  = (const float*)d_in[0];
    const int*   ni = (const int*)d_in[1];
    const int*   hi = (const int*)d_in[2];
    const float* Wk = (const float*)d_in[3];
    const float* bk = (const float*)d_in[4];
    const float* Wq = (const float*)d_in[5];
    const float* bq = (const float*)d_in[6];
    const float* Wa = (const float*)d_in[7];
    const float* ba = (const float*)d_in[8];
    float* out = (float*)d_out;

    int* d_cnt_he; cudaGetSymbolAddress((void**)&d_cnt_he, g_cnt_he);
    int* d_cnt_n;  cudaGetSymbolAddress((void**)&d_cnt_n,  g_cnt_n);
    int* d_off_he; cudaGetSymbolAddress((void**)&d_off_he, g_off_he);
    int* d_off_n;  cudaGetSymbolAddress((void**)&d_off_n,  g_off_n);
    int* d_cur_he; cudaGetSymbolAddress((void**)&d_cur_he, g_cur_he);
    int* d_cur_n;  cudaGetSymbolAddress((void**)&d_cur_n,  g_cur_n);

    float* d_hnode; cudaGetSymbolAddress((void**)&d_hnode, g_hnode);
    float* d_q;     cudaGetSymbolAddress((void**)&d_q,     g_q);
    float* d_resid; cudaGetSymbolAddress((void**)&d_resid, g_resid);

    const int B_HE = (NHE + 1023) / 1024;   // 20
    const int B_N  = (NN + 1023) / 1024;    // 98
    const int GEMM_GRID = (NN + 127) / 128; // 782

    static cudaStream_t s1 = nullptr;
    static cudaEvent_t evFork = nullptr, evHE = nullptr, evN = nullptr;
    if (!s1) {
        cudaStreamCreateWithFlags(&s1, cudaStreamNonBlocking);
        cudaEventCreateWithFlags(&evFork, cudaEventDisableTiming);
        cudaEventCreateWithFlags(&evHE, cudaEventDisableTiming);
        cudaEventCreateWithFlags(&evN, cudaEventDisableTiming);
    }

    // fork
    cudaEventRecord(evFork, 0);
    cudaStreamWaitEvent(s1, evFork, 0);

    // side stream: CSR build (he side first so heagg can start early)
    k_zero<<<(NN + 255) / 256, 256, 0, s1>>>();
    k_hist<<<(EE + 255) / 256, 256, 0, s1>>>(ni, hi);
    k_scan_blk<<<B_HE, 1024, 0, s1>>>(d_cnt_he, d_off_he, NHE);
    k_scan_top<<<1, 128, 0, s1>>>(B_HE);
    k_scan_add<<<B_HE, 1024, 0, s1>>>(d_off_he, d_cur_he, NHE);
    k_scatter_he<<<(EE + 255) / 256, 256, 0, s1>>>(ni, hi);
    cudaEventRecord(evHE, s1);
    k_scan_blk<<<B_N, 1024, 0, s1>>>(d_cnt_n, d_off_n, NN);
    k_scan_top<<<1, 128, 0, s1>>>(B_N);
    k_scan_add<<<B_N, 1024, 0, s1>>>(d_off_n, d_cur_n, NN);
    k_scatter_n<<<(EE + 255) / 256, 256, 0, s1>>>(ni, hi);
    cudaEventRecord(evN, s1);

    // main stream: TF32 GEMMs (K first — heagg needs it)
    k_gemm_tf32<<<GEMM_GRID, 256>>>(x, Wk, bk, d_hnode);
    k_gemm_tf32<<<GEMM_GRID, 256>>>(x, Wq, bq, d_q);

    // heagg overlaps node-side CSR build
    cudaStreamWaitEvent(0, evHE, 0);
    k_heagg<<<NHE * 32 / 256, 256>>>();
    cudaStreamWaitEvent(0, evN, 0);
    k_attn<<<NN * 32 / 256, 256>>>(x);
    k_gemm_tf32<<<GEMM_GRID, 256>>>(d_resid, Wa, ba, out);
}